// round 6
// baseline (speedup 1.0000x reference)
#include <cuda_runtime.h>
#include <cstdint>

#define NN   20000
#define EE   100000
#define NF   8
#define FIN  1024
#define FOUT 512
#define KTOT 1120            // FIN + NF*12
#define NBK  (1u<<20)        // buckets per filtration
#define SHIFT 12
#define UFB  8               // union-find blocks
#define GM_MT 157            // ceil(20000/128)
#define GM_NT 4              // 512/128
#define FUSED_SMEM (NN*8 + 256*20 + 64)   // parent+f + staging + masks

// ---------------- static device scratch (allowed; no allocations) -------------
__device__ float    g_fall[NF*NN];
__device__ int      g_death[NF*NN];
__device__ unsigned g_hist[NF*NBK];
__device__ unsigned g_offs[NF*NBK];
__device__ unsigned g_cur [NF*NBK];
__device__ unsigned g_bsum[NF*1024];
__device__ uint2    g_recs[NF*EE];
__device__ float    g_coord[NN*96];

__device__ __forceinline__ unsigned fkey(float f) {
    unsigned u = __float_as_uint(f);
    return (u & 0x80000000u) ? ~u : (u | 0x80000000u);   // monotone float->uint
}

// ---------------- K0: zero histogram ------------------------------------------
__global__ void k_zero() {
    unsigned i = blockIdx.x * blockDim.x + threadIdx.x;
    if (i < NF*NBK) g_hist[i] = 0u;
}

// ---------------- K1: f_all = x @ filt_w^T + filt_b ----------------------------
__global__ void k_filt(const float* __restrict__ x, const float* __restrict__ fw,
                       const float* __restrict__ fb) {
    __shared__ float ws[NF*FIN];                       // 32 KB
    for (int i = threadIdx.x; i < NF*FIN; i += blockDim.x) ws[i] = fw[i];
    __syncthreads();
    int warp = threadIdx.x >> 5, lane = threadIdx.x & 31;
    int v = blockIdx.x * 8 + warp;
    if (v >= NN) return;
    float acc[NF];
    #pragma unroll
    for (int f = 0; f < NF; f++) acc[f] = 0.f;
    const float* xr = x + (size_t)v * FIN;
    for (int j = lane; j < FIN; j += 32) {
        float xv = xr[j];
        #pragma unroll
        for (int f = 0; f < NF; f++) acc[f] += xv * ws[f*FIN + j];
    }
    #pragma unroll
    for (int f = 0; f < NF; f++) {
        float a = acc[f];
        #pragma unroll
        for (int o = 16; o > 0; o >>= 1) a += __shfl_down_sync(0xffffffffu, a, o);
        if (lane == 0) g_fall[f*NN + v] = a + fb[f];
    }
}

// ---------------- K2: histogram of edge keys ----------------------------------
__global__ void k_hist(const int* __restrict__ ei) {
    unsigned idx = blockIdx.x * blockDim.x + threadIdx.x;
    if (idx >= NF*EE) return;
    unsigned f = idx / EE, e = idx % EE;
    int u = ei[e], v = ei[EE + e];
    float fu = g_fall[f*NN + u], fv = g_fall[f*NN + v];
    unsigned key = fkey(fmaxf(fu, fv));
    atomicAdd(&g_hist[f*NBK + (key >> SHIFT)], 1u);
}

// ---------------- K3a/b/c: segmented exclusive scan ---------------------------
__device__ __forceinline__ unsigned block_excl_scan_1024(unsigned v, unsigned* wsum) {
    unsigned incl = v;
    int lane = threadIdx.x & 31, wp = threadIdx.x >> 5;
    #pragma unroll
    for (int d = 1; d < 32; d <<= 1) {
        unsigned t = __shfl_up_sync(0xffffffffu, incl, d);
        if (lane >= d) incl += t;
    }
    if (lane == 31) wsum[wp] = incl;
    __syncthreads();
    if (wp == 0) {
        unsigned s = wsum[lane], si = s;
        #pragma unroll
        for (int d = 1; d < 32; d <<= 1) {
            unsigned t = __shfl_up_sync(0xffffffffu, si, d);
            if (lane >= d) si += t;
        }
        wsum[lane] = si - s;
    }
    __syncthreads();
    return incl - v + wsum[wp];
}

__global__ void k_scan1() {
    __shared__ unsigned wsum[32];
    unsigned gi = blockIdx.x * 1024u + threadIdx.x;
    unsigned v = g_hist[gi];
    unsigned excl = block_excl_scan_1024(v, wsum);
    g_offs[gi] = excl;
    if (threadIdx.x == 1023) g_bsum[blockIdx.x] = excl + v;
}

__global__ void k_scan2() {   // NF blocks
    __shared__ unsigned wsum[32];
    unsigned gi = blockIdx.x * 1024u + threadIdx.x;
    unsigned v = g_bsum[gi];
    unsigned excl = block_excl_scan_1024(v, wsum);
    g_bsum[gi] = excl;
}

__global__ void k_scan3() {
    unsigned gi = blockIdx.x * 1024u + threadIdx.x;
    unsigned v = g_offs[gi] + g_bsum[blockIdx.x];
    g_offs[gi] = v;
    g_cur[gi]  = v;
}

// ---------------- K4: scatter edges into bucket-grouped records ---------------
__global__ void k_scatter(const int* __restrict__ ei) {
    unsigned idx = blockIdx.x * blockDim.x + threadIdx.x;
    if (idx >= NF*EE) return;
    unsigned f = idx / EE, e = idx % EE;
    int u = ei[e], v = ei[EE + e];
    float fu = g_fall[f*NN + u], fv = g_fall[f*NN + v];
    unsigned key = fkey(fmaxf(fu, fv));
    unsigned dbit = (fu >= fv) ? 0u : 1u;          // death idx = u if fu>=fv else v
    unsigned pos = atomicAdd(&g_cur[f*NBK + (key >> SHIFT)], 1u);
    g_recs[(size_t)f*EE + pos] =
        make_uint2(key, (unsigned)u | ((unsigned)v << 15) | (dbit << 30));
}

// ---------------- K4.5: sort inside each (tiny) bucket ------------------------
__global__ void k_bsort() {
    unsigned idx = blockIdx.x * blockDim.x + threadIdx.x;
    if (idx >= NF*NBK) return;
    unsigned s = g_offs[idx], e2 = g_cur[idx];     // g_cur now = bucket end
    if (e2 - s < 2) return;
    unsigned f = idx >> 20;
    uint2* r = g_recs + (size_t)f*EE;
    for (unsigned i = s + 1; i < e2; i++) {
        uint2 key = r[i];
        int j = (int)i - 1;
        while (j >= (int)s && r[j].x > key.x) { r[j+1] = r[j]; j--; }
        r[j+1] = key;
    }
}

// ---------------- K5: fused union-find + coord (8 blocks) + x@W1 GEMM ---------
__global__ void __launch_bounds__(256, 1)
k_fused(const float* __restrict__ x, const float* __restrict__ ow,
        const float* __restrict__ ob, float* __restrict__ out,
        const float* __restrict__ tri, const float* __restrict__ gmu,
        const float* __restrict__ gsig, const float* __restrict__ lw,
        const float* __restrict__ rc, const float* __restrict__ rr) {
    extern __shared__ char dsm[];
    int tid = threadIdx.x;

    if (blockIdx.x < UFB) {
        // ------- union-find: hinted serial merges + monotone-skip ballot -------
        const int filt = blockIdx.x;
        int*   parent = (int*)dsm;                       // NN ints
        float* fv     = (float*)(dsm + NN*4);            // NN floats
        int*   ha     = (int*)(dsm + NN*8);              // 256
        int*   hb     = ha + 256;
        float* fa     = (float*)(hb + 256);
        float* fbv    = fa + 256;
        unsigned* uvd = (unsigned*)(fbv + 256);
        unsigned* masks = uvd + 256;                     // 8 warp ballot masks

        for (int i = tid; i < NN; i += 256) {
            parent[i] = i;
            fv[i] = g_fall[filt*NN + i];
            g_death[filt*NN + i] = i;
        }
        __syncthreads();

        const uint2* recs = g_recs + (size_t)filt*EE;
        int* deathg = g_death + filt*NN;
        for (int base = 0; base < EE; base += 256) {
            int i = base + tid;
            unsigned flag = 0u;
            if (i < EE) {
                uint2 r = recs[i];
                unsigned w = r.y;
                int u = (int)(w & 0x7FFFu), v = (int)((w >> 15) & 0x7FFFu);
                // path-halving find (racy-safe: only installs ancestors)
                int ra = u;
                for (;;) {
                    int p = parent[ra];
                    if (p == ra) break;
                    int gp = parent[p];
                    parent[ra] = gp;
                    ra = gp;
                }
                int rb = v;
                for (;;) {
                    int p = parent[rb];
                    if (p == rb) break;
                    int gp = parent[p];
                    parent[rb] = gp;
                    rb = gp;
                }
                if (ra != rb) {           // already-connected edges can NEVER merge later
                    flag = 1u;
                    ha[tid] = ra; hb[tid] = rb;
                    fa[tid] = fv[ra]; fbv[tid] = fv[rb];
                    uvd[tid] = w;
                }
            }
            unsigned bal = __ballot_sync(0xffffffffu, flag);
            if ((tid & 31) == 0) masks[tid >> 5] = bal;
            __syncthreads();
            if (tid == 0) {
                #pragma unroll
                for (int wp = 0; wp < 8; wp++) {
                    unsigned mm = masks[wp];
                    while (mm) {
                        int t = wp * 32 + __ffs(mm) - 1;
                        mm &= mm - 1;
                        int ra = ha[t], rb = hb[t];
                        float a = fa[t], b = fbv[t];
                        int p = parent[ra];
                        if (p != ra) {
                            do { ra = p; p = parent[ra]; } while (p != ra);
                            parent[ha[t]] = ra;          // refresh hint path
                            a = fv[ra];
                        }
                        p = parent[rb];
                        if (p != rb) {
                            do { rb = p; p = parent[rb]; } while (p != rb);
                            parent[hb[t]] = rb;
                            b = fv[rb];
                        }
                        if (ra == rb) continue;
                        unsigned w = uvd[t];
                        int di = (w & 0x40000000u) ? (int)((w >> 15) & 0x7FFFu)
                                                   : (int)(w & 0x7FFFu);
                        if (a <= b) { parent[rb] = ra; deathg[rb] = di; }
                        else        { parent[ra] = rb; deathg[ra] = di; }
                    }
                }
            }
            __syncthreads();
        }

        // ------- fused coordinate features for this filtration ----------------
        float t0 = tri[0], t1 = tri[1], t2 = tri[2];
        float sig = gsig[0];
        float inv2s2 = 1.f / (2.f * sig * sig);
        float rrv = fabsf(rr[0]);
        float mu[6], lww[6], rcc[6];
        #pragma unroll
        for (int i = 0; i < 6; i++) { mu[i] = gmu[i]; lww[i] = lw[i]; rcc[i] = rc[i]; }
        for (int n = tid; n < NN; n += 256) {
            float b = fv[n];
            int  di = deathg[n];
            float d = fv[di];
            float* o = g_coord + (size_t)n*96 + filt*12;
            o[0] = fmaxf(0.f, d - fabsf(t0 - b));
            o[1] = fmaxf(0.f, d - fabsf(t1 - b));
            o[2] = fmaxf(0.f, d - fabsf(t2 - b));
            #pragma unroll
            for (int i = 0; i < 3; i++) {
                float dx = b - mu[2*i], dy = d - mu[2*i+1];
                o[3+i] = expf(-(dx*dx + dy*dy) * inv2s2);
            }
            #pragma unroll
            for (int i = 0; i < 3; i++) o[6+i] = b*lww[2*i] + d*lww[2*i+1];
            #pragma unroll
            for (int i = 0; i < 3; i++) {
                float q = fabsf(b - rcc[2*i]) + fabsf(d - rcc[2*i+1]);
                o[9+i] = 1.f/(1.f + q) - 1.f/(1.f + fabsf(rrv - q));
            }
        }
    } else {
        // ----------------- out = x @ W1^T + b  (128x128 tile, fp32) -------------
        int bid = blockIdx.x - UFB;
        int row0 = (bid >> 2) * 128, col0 = (bid & 3) * 128;
        float* As = (float*)dsm;            // [16][128]
        float* Bs = As + 16*128;            // [16][128]
        float acc[8][8];
        #pragma unroll
        for (int i = 0; i < 8; i++)
            #pragma unroll
            for (int j = 0; j < 8; j++) acc[i][j] = 0.f;
        int tx = tid & 15, ty = tid >> 4;

        for (int k0 = 0; k0 < FIN; k0 += 16) {
            {   // load A (x) : 128 rows x 16 k
                int r0t = tid >> 2;
                int kq  = (tid & 3) << 2;
                #pragma unroll
                for (int rr2 = 0; rr2 < 2; rr2++) {
                    int r = r0t + rr2*64;
                    int grow = row0 + r;
                    float4 v4 = (grow < NN)
                        ? *(const float4*)(x + (size_t)grow*FIN + k0 + kq)
                        : make_float4(0.f,0.f,0.f,0.f);
                    As[(kq+0)*128 + r] = v4.x; As[(kq+1)*128 + r] = v4.y;
                    As[(kq+2)*128 + r] = v4.z; As[(kq+3)*128 + r] = v4.w;
                }
            }
            {   // load B (out_w first 1024 cols)
                int c  = tid & 127;
                int kh = (tid >> 7) << 3;
                const float* wp = ow + (size_t)(col0 + c)*KTOT + k0 + kh;
                float4 b0 = *(const float4*)wp;
                float4 b1 = *(const float4*)(wp + 4);
                Bs[(kh+0)*128 + c] = b0.x; Bs[(kh+1)*128 + c] = b0.y;
                Bs[(kh+2)*128 + c] = b0.z; Bs[(kh+3)*128 + c] = b0.w;
                Bs[(kh+4)*128 + c] = b1.x; Bs[(kh+5)*128 + c] = b1.y;
                Bs[(kh+6)*128 + c] = b1.z; Bs[(kh+7)*128 + c] = b1.w;
            }
            __syncthreads();
            #pragma unroll
            for (int kk = 0; kk < 16; kk++) {
                float ar[8], br[8];
                #pragma unroll
                for (int i = 0; i < 8; i++) {
                    ar[i] = As[kk*128 + ty*8 + i];
                    br[i] = Bs[kk*128 + tx*8 + i];
                }
                #pragma unroll
                for (int i = 0; i < 8; i++)
                    #pragma unroll
                    for (int j = 0; j < 8; j++) acc[i][j] += ar[i] * br[j];
            }
            __syncthreads();
        }
        #pragma unroll
        for (int i = 0; i < 8; i++) {
            int r = row0 + ty*8 + i;
            if (r < NN) {
                #pragma unroll
                for (int j = 0; j < 8; j++) {
                    int c = col0 + tx*8 + j;
                    out[(size_t)r*FOUT + c] = acc[i][j] + ob[c];
                }
            }
        }
    }
}

// ---------------- K7: out += coord @ W2^T -------------------------------------
__global__ void k_out(const float* __restrict__ ow, float* __restrict__ out) {
    __shared__ float cs[32*96];
    int n0 = blockIdx.x * 32;
    for (int i = threadIdx.x; i < 32*96; i += blockDim.x)
        cs[i] = g_coord[(size_t)n0*96 + i];
    __syncthreads();
    int o = threadIdx.x;                      // 512 threads = FOUT
    float acc[32];
    #pragma unroll
    for (int i = 0; i < 32; i++) acc[i] = 0.f;
    const float* wr = ow + (size_t)o*KTOT + FIN;
    for (int k = 0; k < 96; k++) {
        float w = wr[k];
        #pragma unroll
        for (int i = 0; i < 32; i++) acc[i] += cs[i*96 + k] * w;
    }
    #pragma unroll
    for (int i = 0; i < 32; i++)
        out[(size_t)(n0 + i)*FOUT + o] += acc[i];
}

// ---------------- launcher ----------------------------------------------------
extern "C" void kernel_launch(void* const* d_in, const int* in_sizes, int n_in,
                              void* d_out, int out_size) {
    const float* x    = (const float*)d_in[0];
    const int*   ei   = (const int*)  d_in[1];
    const float* fw   = (const float*)d_in[2];
    const float* fb   = (const float*)d_in[3];
    const float* tri  = (const float*)d_in[4];
    const float* gmu  = (const float*)d_in[5];
    const float* gsig = (const float*)d_in[6];
    const float* lw   = (const float*)d_in[7];
    const float* rc   = (const float*)d_in[8];
    const float* rr   = (const float*)d_in[9];
    const float* ow   = (const float*)d_in[10];
    const float* ob   = (const float*)d_in[11];
    float* out = (float*)d_out;

    cudaFuncSetAttribute(k_fused, cudaFuncAttributeMaxDynamicSharedMemorySize,
                         FUSED_SMEM);

    k_zero   <<<NF*1024, 1024>>>();
    k_filt   <<<(NN + 7) / 8, 256>>>(x, fw, fb);
    k_hist   <<<(NF*EE + 255) / 256, 256>>>(ei);
    k_scan1  <<<NF*1024, 1024>>>();
    k_scan2  <<<NF, 1024>>>();
    k_scan3  <<<NF*1024, 1024>>>();
    k_scatter<<<(NF*EE + 255) / 256, 256>>>(ei);
    k_bsort  <<<(NF*NBK + 255) / 256, 256>>>();
    k_fused  <<<UFB + GM_MT*GM_NT, 256, FUSED_SMEM>>>(x, ow, ob, out,
                                                      tri, gmu, gsig, lw, rc, rr);
    k_out    <<<NN / 32, 512>>>(ow, out);
}

// round 7
// speedup vs baseline: 1.0613x; 1.0613x over previous
#include <cuda_runtime.h>
#include <cstdint>

#define NN   20000
#define EE   100000
#define NF   8
#define FIN  1024
#define FOUT 512
#define KTOT 1120            // FIN + NF*12
#define NBK  (1u<<20)        // buckets per filtration
#define SHIFT 12
#define UFB  8               // union-find blocks
#define GM_MT 157            // ceil(20000/128)
#define GM_NT 4              // 512/128
#define HSLOTS 4096
// parent+f (160000) + staging (5120) + masks (32) + hash (16384)
#define FUSED_SMEM (NN*8 + 256*20 + 32 + HSLOTS*4)

// ---------------- static device scratch (allowed; no allocations) -------------
__device__ float    g_fall[NF*NN];
__device__ int      g_death[NF*NN];
__device__ unsigned g_hist[NF*NBK];
__device__ unsigned g_offs[NF*NBK];
__device__ unsigned g_cur [NF*NBK];
__device__ unsigned g_bsum[NF*1024];
__device__ uint2    g_recs[NF*EE];
__device__ float    g_coord[NN*96];

__device__ __forceinline__ unsigned fkey(float f) {
    unsigned u = __float_as_uint(f);
    return (u & 0x80000000u) ? ~u : (u | 0x80000000u);   // monotone float->uint
}

__device__ __forceinline__ unsigned hsh(int r) {
    return ((unsigned)r * 2654435761u) >> 20;            // 12 bits -> 4096 slots
}

// ---------------- K0: zero histogram ------------------------------------------
__global__ void k_zero() {
    unsigned i = blockIdx.x * blockDim.x + threadIdx.x;
    if (i < NF*NBK) g_hist[i] = 0u;
}

// ---------------- K1: f_all = x @ filt_w^T + filt_b ----------------------------
__global__ void k_filt(const float* __restrict__ x, const float* __restrict__ fw,
                       const float* __restrict__ fb) {
    __shared__ float ws[NF*FIN];                       // 32 KB
    for (int i = threadIdx.x; i < NF*FIN; i += blockDim.x) ws[i] = fw[i];
    __syncthreads();
    int warp = threadIdx.x >> 5, lane = threadIdx.x & 31;
    int v = blockIdx.x * 8 + warp;
    if (v >= NN) return;
    float acc[NF];
    #pragma unroll
    for (int f = 0; f < NF; f++) acc[f] = 0.f;
    const float* xr = x + (size_t)v * FIN;
    for (int j = lane; j < FIN; j += 32) {
        float xv = xr[j];
        #pragma unroll
        for (int f = 0; f < NF; f++) acc[f] += xv * ws[f*FIN + j];
    }
    #pragma unroll
    for (int f = 0; f < NF; f++) {
        float a = acc[f];
        #pragma unroll
        for (int o = 16; o > 0; o >>= 1) a += __shfl_down_sync(0xffffffffu, a, o);
        if (lane == 0) g_fall[f*NN + v] = a + fb[f];
    }
}

// ---------------- K2: histogram of edge keys ----------------------------------
__global__ void k_hist(const int* __restrict__ ei) {
    unsigned idx = blockIdx.x * blockDim.x + threadIdx.x;
    if (idx >= NF*EE) return;
    unsigned f = idx / EE, e = idx % EE;
    int u = ei[e], v = ei[EE + e];
    float fu = g_fall[f*NN + u], fv = g_fall[f*NN + v];
    unsigned key = fkey(fmaxf(fu, fv));
    atomicAdd(&g_hist[f*NBK + (key >> SHIFT)], 1u);
}

// ---------------- K3a/b/c: segmented exclusive scan ---------------------------
__device__ __forceinline__ unsigned block_excl_scan_1024(unsigned v, unsigned* wsum) {
    unsigned incl = v;
    int lane = threadIdx.x & 31, wp = threadIdx.x >> 5;
    #pragma unroll
    for (int d = 1; d < 32; d <<= 1) {
        unsigned t = __shfl_up_sync(0xffffffffu, incl, d);
        if (lane >= d) incl += t;
    }
    if (lane == 31) wsum[wp] = incl;
    __syncthreads();
    if (wp == 0) {
        unsigned s = wsum[lane], si = s;
        #pragma unroll
        for (int d = 1; d < 32; d <<= 1) {
            unsigned t = __shfl_up_sync(0xffffffffu, si, d);
            if (lane >= d) si += t;
        }
        wsum[lane] = si - s;
    }
    __syncthreads();
    return incl - v + wsum[wp];
}

__global__ void k_scan1() {
    __shared__ unsigned wsum[32];
    unsigned gi = blockIdx.x * 1024u + threadIdx.x;
    unsigned v = g_hist[gi];
    unsigned excl = block_excl_scan_1024(v, wsum);
    g_offs[gi] = excl;
    if (threadIdx.x == 1023) g_bsum[blockIdx.x] = excl + v;
}

__global__ void k_scan2() {   // NF blocks
    __shared__ unsigned wsum[32];
    unsigned gi = blockIdx.x * 1024u + threadIdx.x;
    unsigned v = g_bsum[gi];
    unsigned excl = block_excl_scan_1024(v, wsum);
    g_bsum[gi] = excl;
}

__global__ void k_scan3() {
    unsigned gi = blockIdx.x * 1024u + threadIdx.x;
    unsigned v = g_offs[gi] + g_bsum[blockIdx.x];
    g_offs[gi] = v;
    g_cur[gi]  = v;
}

// ---------------- K4: scatter edges into bucket-grouped records ---------------
__global__ void k_scatter(const int* __restrict__ ei) {
    unsigned idx = blockIdx.x * blockDim.x + threadIdx.x;
    if (idx >= NF*EE) return;
    unsigned f = idx / EE, e = idx % EE;
    int u = ei[e], v = ei[EE + e];
    float fu = g_fall[f*NN + u], fv = g_fall[f*NN + v];
    unsigned key = fkey(fmaxf(fu, fv));
    unsigned dbit = (fu >= fv) ? 0u : 1u;          // death idx = u if fu>=fv else v
    unsigned pos = atomicAdd(&g_cur[f*NBK + (key >> SHIFT)], 1u);
    g_recs[(size_t)f*EE + pos] =
        make_uint2(key, (unsigned)u | ((unsigned)v << 15) | (dbit << 30));
}

// ---------------- K4.5: sort inside each (tiny) bucket ------------------------
__global__ void k_bsort() {
    unsigned idx = blockIdx.x * blockDim.x + threadIdx.x;
    if (idx >= NF*NBK) return;
    unsigned s = g_offs[idx], e2 = g_cur[idx];     // g_cur now = bucket end
    if (e2 - s < 2) return;
    unsigned f = idx >> 20;
    uint2* r = g_recs + (size_t)f*EE;
    for (unsigned i = s + 1; i < e2; i++) {
        uint2 key = r[i];
        int j = (int)i - 1;
        while (j >= (int)s && r[j].x > key.x) { r[j+1] = r[j]; j--; }
        r[j+1] = key;
    }
}

// ---------------- K5: fused UF (parallel merges + serial conflicts) + GEMM ----
__global__ void __launch_bounds__(256, 1)
k_fused(const float* __restrict__ x, const float* __restrict__ ow,
        const float* __restrict__ ob, float* __restrict__ out,
        const float* __restrict__ tri, const float* __restrict__ gmu,
        const float* __restrict__ gsig, const float* __restrict__ lw,
        const float* __restrict__ rc, const float* __restrict__ rr) {
    extern __shared__ char dsm[];
    int tid = threadIdx.x;

    if (blockIdx.x < UFB) {
        const int filt = blockIdx.x;
        int*   parent = (int*)dsm;                       // NN ints
        float* fv     = (float*)(dsm + NN*4);            // NN floats
        int*   ha     = (int*)(dsm + NN*8);              // 256
        int*   hb     = ha + 256;
        float* fa     = (float*)(hb + 256);
        float* fbv    = fa + 256;
        unsigned* uvd = (unsigned*)(fbv + 256);
        unsigned* masks = uvd + 256;                     // 8 warp ballot masks
        unsigned* hcnt  = masks + 8;                     // 4096 hash counters

        for (int i = tid; i < NN; i += 256) {
            parent[i] = i;
            fv[i] = g_fall[filt*NN + i];
            g_death[filt*NN + i] = i;
        }
        for (int i = tid; i < HSLOTS; i += 256) hcnt[i] = 0u;
        __syncthreads();

        const uint2* recs = g_recs + (size_t)filt*EE;
        int* deathg = g_death + filt*NN;

        for (int base = 0; base < EE; base += 256) {
            int i = base + tid;
            unsigned flag = 0u, w = 0u;
            int ra = 0, rb = 0;

            // -------- Phase A: find both roots (racy-safe compression) --------
            if (i < EE) {
                uint2 r = recs[i];
                w = r.y;
                int u = (int)(w & 0x7FFFu), v = (int)((w >> 15) & 0x7FFFu);
                int p;
                ra = u;
                while ((p = parent[ra]) != ra) ra = p;
                int xx = u;
                while (xx != ra) { int nx = parent[xx]; parent[xx] = ra; xx = nx; }
                rb = v;
                while ((p = parent[rb]) != rb) rb = p;
                xx = v;
                while (xx != rb) { int nx = parent[xx]; parent[xx] = rb; xx = nx; }
                if (ra != rb) {     // already-connected edges can never merge later
                    flag = 1u;
                    ha[tid] = ra; hb[tid] = rb;
                    fa[tid] = fv[ra]; fbv[tid] = fv[rb];
                    uvd[tid] = w;
                }
            }
            __syncthreads();

            // -------- Phase B: count root usage in shared hash ----------------
            if (flag) {
                atomicAdd(&hcnt[hsh(ra)], 1u);
                atomicAdd(&hcnt[hsh(rb)], 1u);
            }
            __syncthreads();

            // -------- Phase C: exclusive edges merge in parallel --------------
            unsigned conflict = 0u;
            if (flag) {
                if (hcnt[hsh(ra)] == 1u && hcnt[hsh(rb)] == 1u) {
                    // no other flagged edge in this batch touches ra or rb:
                    // merge commutes with everything else in the batch
                    float a = fa[tid], b = fbv[tid];
                    int di = (w & 0x40000000u) ? (int)((w >> 15) & 0x7FFFu)
                                               : (int)(w & 0x7FFFu);
                    if (a <= b) { parent[rb] = ra; deathg[rb] = di; }
                    else        { parent[ra] = rb; deathg[ra] = di; }
                } else {
                    conflict = 1u;
                }
            }
            unsigned bal = __ballot_sync(0xffffffffu, conflict);
            if ((tid & 31) == 0) masks[tid >> 5] = bal;
            __syncthreads();

            // -------- Phase D: serial thread resolves conflicts in order ------
            if (tid == 0) {
                #pragma unroll
                for (int wp = 0; wp < 8; wp++) {
                    unsigned mm = masks[wp];
                    while (mm) {
                        int t = wp * 32 + __ffs(mm) - 1;
                        mm &= mm - 1;
                        int a1 = ha[t], b1 = hb[t], p;
                        while ((p = parent[a1]) != a1) a1 = p;
                        while ((p = parent[b1]) != b1) b1 = p;
                        if (a1 == b1) continue;
                        float a = fv[a1], b = fv[b1];
                        unsigned ww = uvd[t];
                        int di = (ww & 0x40000000u) ? (int)((ww >> 15) & 0x7FFFu)
                                                    : (int)(ww & 0x7FFFu);
                        if (a <= b) { parent[b1] = a1; deathg[b1] = di; }
                        else        { parent[a1] = b1; deathg[a1] = di; }
                    }
                }
            } else {
                // other threads clear the hash for the next batch
                for (int s = tid - 1; s < HSLOTS; s += 255) hcnt[s] = 0u;
            }
            __syncthreads();
        }

        // ------- fused coordinate features for this filtration ----------------
        float t0 = tri[0], t1 = tri[1], t2 = tri[2];
        float sig = gsig[0];
        float inv2s2 = 1.f / (2.f * sig * sig);
        float rrv = fabsf(rr[0]);
        float mu[6], lww[6], rcc[6];
        #pragma unroll
        for (int i = 0; i < 6; i++) { mu[i] = gmu[i]; lww[i] = lw[i]; rcc[i] = rc[i]; }
        for (int n = tid; n < NN; n += 256) {
            float b = fv[n];
            int  di = deathg[n];
            float d = fv[di];
            float* o = g_coord + (size_t)n*96 + filt*12;
            o[0] = fmaxf(0.f, d - fabsf(t0 - b));
            o[1] = fmaxf(0.f, d - fabsf(t1 - b));
            o[2] = fmaxf(0.f, d - fabsf(t2 - b));
            #pragma unroll
            for (int i = 0; i < 3; i++) {
                float dx = b - mu[2*i], dy = d - mu[2*i+1];
                o[3+i] = expf(-(dx*dx + dy*dy) * inv2s2);
            }
            #pragma unroll
            for (int i = 0; i < 3; i++) o[6+i] = b*lww[2*i] + d*lww[2*i+1];
            #pragma unroll
            for (int i = 0; i < 3; i++) {
                float q = fabsf(b - rcc[2*i]) + fabsf(d - rcc[2*i+1]);
                o[9+i] = 1.f/(1.f + q) - 1.f/(1.f + fabsf(rrv - q));
            }
        }
    } else {
        // ----------------- out = x @ W1^T + b  (128x128 tile, fp32) -------------
        int bid = blockIdx.x - UFB;
        int row0 = (bid >> 2) * 128, col0 = (bid & 3) * 128;
        float* As = (float*)dsm;            // [16][128]
        float* Bs = As + 16*128;            // [16][128]
        float acc[8][8];
        #pragma unroll
        for (int i = 0; i < 8; i++)
            #pragma unroll
            for (int j = 0; j < 8; j++) acc[i][j] = 0.f;
        int tx = tid & 15, ty = tid >> 4;

        for (int k0 = 0; k0 < FIN; k0 += 16) {
            {   // load A (x) : 128 rows x 16 k
                int r0t = tid >> 2;
                int kq  = (tid & 3) << 2;
                #pragma unroll
                for (int rr2 = 0; rr2 < 2; rr2++) {
                    int r = r0t + rr2*64;
                    int grow = row0 + r;
                    float4 v4 = (grow < NN)
                        ? *(const float4*)(x + (size_t)grow*FIN + k0 + kq)
                        : make_float4(0.f,0.f,0.f,0.f);
                    As[(kq+0)*128 + r] = v4.x; As[(kq+1)*128 + r] = v4.y;
                    As[(kq+2)*128 + r] = v4.z; As[(kq+3)*128 + r] = v4.w;
                }
            }
            {   // load B (out_w first 1024 cols)
                int c  = tid & 127;
                int kh = (tid >> 7) << 3;
                const float* wp = ow + (size_t)(col0 + c)*KTOT + k0 + kh;
                float4 b0 = *(const float4*)wp;
                float4 b1 = *(const float4*)(wp + 4);
                Bs[(kh+0)*128 + c] = b0.x; Bs[(kh+1)*128 + c] = b0.y;
                Bs[(kh+2)*128 + c] = b0.z; Bs[(kh+3)*128 + c] = b0.w;
                Bs[(kh+4)*128 + c] = b1.x; Bs[(kh+5)*128 + c] = b1.y;
                Bs[(kh+6)*128 + c] = b1.z; Bs[(kh+7)*128 + c] = b1.w;
            }
            __syncthreads();
            #pragma unroll
            for (int kk = 0; kk < 16; kk++) {
                float ar[8], br[8];
                #pragma unroll
                for (int i = 0; i < 8; i++) {
                    ar[i] = As[kk*128 + ty*8 + i];
                    br[i] = Bs[kk*128 + tx*8 + i];
                }
                #pragma unroll
                for (int i = 0; i < 8; i++)
                    #pragma unroll
                    for (int j = 0; j < 8; j++) acc[i][j] += ar[i] * br[j];
            }
            __syncthreads();
        }
        #pragma unroll
        for (int i = 0; i < 8; i++) {
            int r = row0 + ty*8 + i;
            if (r < NN) {
                #pragma unroll
                for (int j = 0; j < 8; j++) {
                    int c = col0 + tx*8 + j;
                    out[(size_t)r*FOUT + c] = acc[i][j] + ob[c];
                }
            }
        }
    }
}

// ---------------- K7: out += coord @ W2^T -------------------------------------
__global__ void k_out(const float* __restrict__ ow, float* __restrict__ out) {
    __shared__ float cs[32*96];
    int n0 = blockIdx.x * 32;
    for (int i = threadIdx.x; i < 32*96; i += blockDim.x)
        cs[i] = g_coord[(size_t)n0*96 + i];
    __syncthreads();
    int o = threadIdx.x;                      // 512 threads = FOUT
    float acc[32];
    #pragma unroll
    for (int i = 0; i < 32; i++) acc[i] = 0.f;
    const float* wr = ow + (size_t)o*KTOT + FIN;
    for (int k = 0; k < 96; k++) {
        float w = wr[k];
        #pragma unroll
        for (int i = 0; i < 32; i++) acc[i] += cs[i*96 + k] * w;
    }
    #pragma unroll
    for (int i = 0; i < 32; i++)
        out[(size_t)(n0 + i)*FOUT + o] += acc[i];
}

// ---------------- launcher ----------------------------------------------------
extern "C" void kernel_launch(void* const* d_in, const int* in_sizes, int n_in,
                              void* d_out, int out_size) {
    const float* x    = (const float*)d_in[0];
    const int*   ei   = (const int*)  d_in[1];
    const float* fw   = (const float*)d_in[2];
    const float* fb   = (const float*)d_in[3];
    const float* tri  = (const float*)d_in[4];
    const float* gmu  = (const float*)d_in[5];
    const float* gsig = (const float*)d_in[6];
    const float* lw   = (const float*)d_in[7];
    const float* rc   = (const float*)d_in[8];
    const float* rr   = (const float*)d_in[9];
    const float* ow   = (const float*)d_in[10];
    const float* ob   = (const float*)d_in[11];
    float* out = (float*)d_out;

    cudaFuncSetAttribute(k_fused, cudaFuncAttributeMaxDynamicSharedMemorySize,
                         FUSED_SMEM);

    k_zero   <<<NF*1024, 1024>>>();
    k_filt   <<<(NN + 7) / 8, 256>>>(x, fw, fb);
    k_hist   <<<(NF*EE + 255) / 256, 256>>>(ei);
    k_scan1  <<<NF*1024, 1024>>>();
    k_scan2  <<<NF, 1024>>>();
    k_scan3  <<<NF*1024, 1024>>>();
    k_scatter<<<(NF*EE + 255) / 256, 256>>>(ei);
    k_bsort  <<<(NF*NBK + 255) / 256, 256>>>();
    k_fused  <<<UFB + GM_MT*GM_NT, 256, FUSED_SMEM>>>(x, ow, ob, out,
                                                      tri, gmu, gsig, lw, rc, rr);
    k_out    <<<NN / 32, 512>>>(ow, out);
}

// round 11
// speedup vs baseline: 4.3403x; 4.0895x over previous
#include <cuda_runtime.h>
#include <cstdint>

#define NN   20000
#define EE   100000
#define NF   8
#define FIN  1024
#define FOUT 512
#define KTOT 1120            // FIN + NF*12
#define NBK  (1u<<20)        // buckets per filtration
#define SHIFT 12
#define UFB  8               // union-find blocks
#define GM_MT 157            // ceil(20000/128)
#define GM_NT 4              // 512/128
#define TIL  391             // ceil(EE/256)
#define BVR  15              // Boruvka rounds (2^15 > 20000)
#define AL_W 3125            // ceil(EE/32) alive-bitmap words
#define FUSED_SMEM (NN*8 + 256*20)          // parent+f + staging
#define BV_SMEM    (NN*4 + NN*4 + AL_W*4)   // parent + minE + alive = 172500
#define RPT 20               // ceil(NN/1024) roots per thread in k_bv

// ---------------- static device scratch (allowed; no allocations) -------------
__device__ float    g_fall[NF*NN];
__device__ int      g_death[NF*NN];
__device__ unsigned g_hist[NF*NBK];
__device__ unsigned g_offs[NF*NBK];
__device__ unsigned g_cur [NF*NBK];
__device__ unsigned g_bsum[NF*1024];
__device__ uint2    g_recs[NF*EE];
__device__ uint2    g_recs2[NF*EE];
__device__ float    g_coord[NN*96];
__device__ unsigned char g_mflag[NF*EE];
__device__ unsigned g_tile[NF*512];
__device__ unsigned g_cnt[NF];

__device__ __forceinline__ unsigned fkey(float f) {
    unsigned u = __float_as_uint(f);
    return (u & 0x80000000u) ? ~u : (u | 0x80000000u);   // monotone float->uint
}

// ---------------- K0: zero histogram ------------------------------------------
__global__ void k_zero() {
    unsigned i = blockIdx.x * blockDim.x + threadIdx.x;
    if (i < NF*NBK) g_hist[i] = 0u;
}

// ---------------- K1: f_all = x @ filt_w^T + filt_b ----------------------------
__global__ void k_filt(const float* __restrict__ x, const float* __restrict__ fw,
                       const float* __restrict__ fb) {
    __shared__ float ws[NF*FIN];                       // 32 KB
    for (int i = threadIdx.x; i < NF*FIN; i += blockDim.x) ws[i] = fw[i];
    __syncthreads();
    int warp = threadIdx.x >> 5, lane = threadIdx.x & 31;
    int v = blockIdx.x * 8 + warp;
    if (v >= NN) return;
    float acc[NF];
    #pragma unroll
    for (int f = 0; f < NF; f++) acc[f] = 0.f;
    const float* xr = x + (size_t)v * FIN;
    for (int j = lane; j < FIN; j += 32) {
        float xv = xr[j];
        #pragma unroll
        for (int f = 0; f < NF; f++) acc[f] += xv * ws[f*FIN + j];
    }
    #pragma unroll
    for (int f = 0; f < NF; f++) {
        float a = acc[f];
        #pragma unroll
        for (int o = 16; o > 0; o >>= 1) a += __shfl_down_sync(0xffffffffu, a, o);
        if (lane == 0) g_fall[f*NN + v] = a + fb[f];
    }
}

// ---------------- K2: histogram of edge keys ----------------------------------
__global__ void k_hist(const int* __restrict__ ei) {
    unsigned idx = blockIdx.x * blockDim.x + threadIdx.x;
    if (idx >= NF*EE) return;
    unsigned f = idx / EE, e = idx % EE;
    int u = ei[e], v = ei[EE + e];
    float fu = g_fall[f*NN + u], fv = g_fall[f*NN + v];
    unsigned key = fkey(fmaxf(fu, fv));
    atomicAdd(&g_hist[f*NBK + (key >> SHIFT)], 1u);
}

// ---------------- K3: segmented exclusive scan --------------------------------
__device__ __forceinline__ unsigned block_excl_scan_1024(unsigned v, unsigned* wsum) {
    unsigned incl = v;
    int lane = threadIdx.x & 31, wp = threadIdx.x >> 5;
    #pragma unroll
    for (int d = 1; d < 32; d <<= 1) {
        unsigned t = __shfl_up_sync(0xffffffffu, incl, d);
        if (lane >= d) incl += t;
    }
    if (lane == 31) wsum[wp] = incl;
    __syncthreads();
    if (wp == 0) {
        unsigned s = wsum[lane], si = s;
        #pragma unroll
        for (int d = 1; d < 32; d <<= 1) {
            unsigned t = __shfl_up_sync(0xffffffffu, si, d);
            if (lane >= d) si += t;
        }
        wsum[lane] = si - s;
    }
    __syncthreads();
    return incl - v + wsum[wp];
}

__global__ void k_scan1() {
    __shared__ unsigned wsum[32];
    unsigned gi = blockIdx.x * 1024u + threadIdx.x;
    unsigned v = g_hist[gi];
    unsigned excl = block_excl_scan_1024(v, wsum);
    g_offs[gi] = excl;
    if (threadIdx.x == 1023) g_bsum[blockIdx.x] = excl + v;
}

__global__ void k_scan2() {   // NF blocks
    __shared__ unsigned wsum[32];
    unsigned gi = blockIdx.x * 1024u + threadIdx.x;
    unsigned v = g_bsum[gi];
    unsigned excl = block_excl_scan_1024(v, wsum);
    g_bsum[gi] = excl;
}

__global__ void k_scan3() {
    unsigned gi = blockIdx.x * 1024u + threadIdx.x;
    unsigned v = g_offs[gi] + g_bsum[blockIdx.x];
    g_offs[gi] = v;
    g_cur[gi]  = v;
}

// ---------------- K4: scatter edges into bucket-grouped records ---------------
__global__ void k_scatter(const int* __restrict__ ei) {
    unsigned idx = blockIdx.x * blockDim.x + threadIdx.x;
    if (idx >= NF*EE) return;
    unsigned f = idx / EE, e = idx % EE;
    int u = ei[e], v = ei[EE + e];
    float fu = g_fall[f*NN + u], fv = g_fall[f*NN + v];
    unsigned key = fkey(fmaxf(fu, fv));
    unsigned dbit = (fu >= fv) ? 0u : 1u;          // death idx = u if fu>=fv else v
    unsigned pos = atomicAdd(&g_cur[f*NBK + (key >> SHIFT)], 1u);
    g_recs[(size_t)f*EE + pos] =
        make_uint2(key, (unsigned)u | ((unsigned)v << 15) | (dbit << 30));
}

// ---------------- K4.5: sort inside each (tiny) bucket ------------------------
__global__ void k_bsort() {
    unsigned idx = blockIdx.x * blockDim.x + threadIdx.x;
    if (idx >= NF*NBK) return;
    unsigned s = g_offs[idx], e2 = g_cur[idx];     // g_cur now = bucket end
    if (e2 - s < 2) return;
    unsigned f = idx >> 20;
    uint2* r = g_recs + (size_t)f*EE;
    for (unsigned i = s + 1; i < e2; i++) {
        uint2 key = r[i];
        int j = (int)i - 1;
        while (j >= (int)s && r[j].x > key.x) { r[j+1] = r[j]; j--; }
        r[j+1] = key;
    }
}

// =================== Boruvka MSF prefilter: one block / filtration ============
// parent[] is FLAT at every phase boundary -> root lookup is one read (no
// walks during concurrent writes => no livelock). Unique weights (sorted edge
// index) => hook cycles are exactly 2-cycles, broken deterministically from a
// frozen hook table. Flagged edges across rounds = the unique MSF = exactly
// the edges that merge in serial Kruskal.
__global__ void __launch_bounds__(1024, 1) k_bv() {
    extern __shared__ char bsm[];
    int*      parent = (int*)bsm;                    // NN
    unsigned* minE   = (unsigned*)(bsm + NN*4);      // NN
    unsigned* alive  = (unsigned*)(bsm + NN*8);      // AL_W words
    const int f = blockIdx.x, tid = threadIdx.x;
    const uint2* recs = g_recs + (size_t)f*EE;
    unsigned char* mf = g_mflag + (size_t)f*EE;

    for (int i = tid; i < NN; i += 1024) { parent[i] = i; minE[i] = 0xFFFFFFFFu; }
    for (int i = tid; i < AL_W; i += 1024) alive[i] = 0xFFFFFFFFu;
    for (int e = tid; e < EE; e += 1024) mf[e] = 0;
    __syncthreads();

    unsigned oth[RPT];
    for (int round = 0; round < BVR; round++) {
        // ---- phase 1: per-edge min-crossing-edge (parent flat, single reads)
        for (int e = tid; e < EE; e += 1024) {
            if (alive[e >> 5] & (1u << (e & 31))) {
                unsigned w = recs[e].y;
                int u = (int)(w & 0x7FFFu), v = (int)((w >> 15) & 0x7FFFu);
                int ra = parent[u], rb = parent[v];
                if (ra == rb) atomicAnd(&alive[e >> 5], ~(1u << (e & 31)));
                else {
                    atomicMin(&minE[ra], (unsigned)e);
                    atomicMin(&minE[rb], (unsigned)e);
                }
            }
        }
        __syncthreads();
        // ---- phase 2a: derive hooks into registers; flag MSF edges
        {
            int k = 0;
            for (int r = tid; r < NN; r += 1024, k++) {
                unsigned o = 0xFFFFFFFFu;
                if (parent[r] == r) {
                    unsigned e = minE[r];
                    if (e != 0xFFFFFFFFu) {
                        unsigned w = recs[e].y;
                        int u = (int)(w & 0x7FFFu), v = (int)((w >> 15) & 0x7FFFu);
                        int ru = parent[u], rv = parent[v];
                        o = (ru == r) ? (unsigned)rv : (unsigned)ru;
                        mf[e] = 1;
                    }
                }
                oth[k] = o;
            }
        }
        __syncthreads();
        // ---- phase 2b: publish hook table (minE repurposed)
        {
            int k = 0;
            for (int r = tid; r < NN; r += 1024, k++) minE[r] = oth[k];
        }
        __syncthreads();
        // ---- phase 2c: commit hooks; break mutual 2-cycles (keep smaller)
        {
            int k = 0;
            for (int r = tid; r < NN; r += 1024, k++) {
                unsigned o = oth[k];
                if (o != 0xFFFFFFFFu && parent[r] == r) {
                    if (!(minE[o] == (unsigned)r && (unsigned)r < o))
                        parent[r] = (int)o;
                }
            }
        }
        __syncthreads();
        // ---- phase 3: pointer-jump flatten (acyclic) + minE reset
        for (int i = tid; i < NN; i += 1024) {
            int r = i, p;
            while ((p = parent[r]) != r) r = p;
            parent[i] = r;
            minE[i] = 0xFFFFFFFFu;
        }
        __syncthreads();
    }
}

// ---------------- compaction (order-preserving) -------------------------------
__global__ void k_cnt() {                           // grid NF*TIL, 256 thr
    __shared__ unsigned wcnt[8];
    unsigned f = blockIdx.x / TIL, tile = blockIdx.x % TIL;
    unsigned i = tile * 256 + threadIdx.x;
    unsigned flag = (i < EE) ? (unsigned)g_mflag[(size_t)f*EE + i] : 0u;
    unsigned bal = __ballot_sync(0xffffffffu, flag);
    if ((threadIdx.x & 31) == 0) wcnt[threadIdx.x >> 5] = __popc(bal);
    __syncthreads();
    if (threadIdx.x == 0) {
        unsigned s = 0;
        #pragma unroll
        for (int w = 0; w < 8; w++) s += wcnt[w];
        g_tile[f*512 + tile] = s;
    }
}

__global__ void k_cscan() {                         // NF blocks, 1024 thr
    __shared__ unsigned wsum[32];
    unsigned f = blockIdx.x;
    unsigned v = (threadIdx.x < TIL) ? g_tile[f*512 + threadIdx.x] : 0u;
    unsigned excl = block_excl_scan_1024(v, wsum);
    if (threadIdx.x < TIL) g_tile[f*512 + threadIdx.x] = excl;
    if (threadIdx.x == TIL - 1) g_cnt[f] = excl + v;
}

__global__ void k_csct() {                          // grid NF*TIL, 256 thr
    __shared__ unsigned woff[8];
    unsigned f = blockIdx.x / TIL, tile = blockIdx.x % TIL;
    unsigned i = tile * 256 + threadIdx.x;
    unsigned flag = (i < EE) ? (unsigned)g_mflag[(size_t)f*EE + i] : 0u;
    unsigned bal = __ballot_sync(0xffffffffu, flag);
    int lane = threadIdx.x & 31, wp = threadIdx.x >> 5;
    if (lane == 0) woff[wp] = __popc(bal);
    __syncthreads();
    if (threadIdx.x == 0) {
        unsigned s = 0;
        #pragma unroll
        for (int w = 0; w < 8; w++) { unsigned t = woff[w]; woff[w] = s; s += t; }
    }
    __syncthreads();
    if (flag) {
        unsigned pos = g_tile[f*512 + tile] + woff[wp]
                     + __popc(bal & ((1u << lane) - 1u));
        g_recs2[(size_t)f*EE + pos] = g_recs[(size_t)f*EE + i];
    }
}

// ---------------- K5: fused UF (validated r2 structure) + x@W1 GEMM -----------
__global__ void __launch_bounds__(256, 1)
k_fused(const float* __restrict__ x, const float* __restrict__ ow,
        const float* __restrict__ ob, float* __restrict__ out) {
    extern __shared__ char dsm[];
    int tid = threadIdx.x;

    if (blockIdx.x < UFB) {
        const int filt = blockIdx.x;
        int*   parent = (int*)dsm;                       // NN ints
        float* fv     = (float*)(dsm + NN*4);            // NN floats
        int*   ha     = (int*)(dsm + NN*8);              // 256
        int*   hb     = ha + 256;
        float* fa     = (float*)(hb + 256);
        float* fbv    = fa + 256;
        unsigned* uvd = (unsigned*)(fbv + 256);

        for (int i = tid; i < NN; i += 256) {
            parent[i] = i;
            fv[i] = g_fall[filt*NN + i];
            g_death[filt*NN + i] = i;
        }
        __syncthreads();

        const int cnt = (int)g_cnt[filt];                // compacted MSF stream
        const uint2* recs = g_recs2 + (size_t)filt*EE;
        for (int base = 0; base < cnt; base += 256) {
            int i = base + tid;
            if (i < cnt) {
                uint2 r = recs[i];
                unsigned w = r.y;
                int u = (int)(w & 0x7FFFu), v = (int)((w >> 15) & 0x7FFFu);
                int ra = u, p;
                while ((p = parent[ra]) != ra) ra = p;
                int xx = u;
                while (xx != ra) { int nx = parent[xx]; parent[xx] = ra; xx = nx; }
                int rb = v;
                while ((p = parent[rb]) != rb) rb = p;
                xx = v;
                while (xx != rb) { int nx = parent[xx]; parent[xx] = rb; xx = nx; }
                ha[tid] = ra; hb[tid] = rb;
                fa[tid] = fv[ra]; fbv[tid] = fv[rb];
                uvd[tid] = w;
            }
            __syncthreads();
            if (tid == 0) {
                int lim = min(256, cnt - base);
                for (int t = 0; t < lim; t++) {
                    int ra = ha[t], rb = hb[t];
                    int pa = parent[ra], pb = parent[rb];
                    float a = fa[t], b = fbv[t];
                    if (pa != ra) { do { ra = pa; pa = parent[ra]; } while (pa != ra); a = fv[ra]; }
                    if (pb != rb) { do { rb = pb; pb = parent[rb]; } while (pb != rb); b = fv[rb]; }
                    if (ra == rb) continue;
                    unsigned w = uvd[t];
                    int di = (w & 0x40000000u) ? (int)((w >> 15) & 0x7FFFu)
                                               : (int)(w & 0x7FFFu);
                    if (a <= b) { parent[rb] = ra; g_death[filt*NN + rb] = di; }
                    else        { parent[ra] = rb; g_death[filt*NN + ra] = di; }
                }
            }
            __syncthreads();
        }
    } else {
        // ----------------- out = x @ W1^T + b  (128x128 tile, fp32) -------------
        int bid = blockIdx.x - UFB;
        int row0 = (bid >> 2) * 128, col0 = (bid & 3) * 128;
        float* As = (float*)dsm;            // [16][128]
        float* Bs = As + 16*128;            // [16][128]
        float acc[8][8];
        #pragma unroll
        for (int i = 0; i < 8; i++)
            #pragma unroll
            for (int j = 0; j < 8; j++) acc[i][j] = 0.f;
        int tx = tid & 15, ty = tid >> 4;

        for (int k0 = 0; k0 < FIN; k0 += 16) {
            {   // load A (x) : 128 rows x 16 k
                int r0t = tid >> 2;
                int kq  = (tid & 3) << 2;
                #pragma unroll
                for (int rr2 = 0; rr2 < 2; rr2++) {
                    int r = r0t + rr2*64;
                    int grow = row0 + r;
                    float4 v4 = (grow < NN)
                        ? *(const float4*)(x + (size_t)grow*FIN + k0 + kq)
                        : make_float4(0.f,0.f,0.f,0.f);
                    As[(kq+0)*128 + r] = v4.x; As[(kq+1)*128 + r] = v4.y;
                    As[(kq+2)*128 + r] = v4.z; As[(kq+3)*128 + r] = v4.w;
                }
            }
            {   // load B (out_w first 1024 cols)
                int c  = tid & 127;
                int kh = (tid >> 7) << 3;
                const float* wp = ow + (size_t)(col0 + c)*KTOT + k0 + kh;
                float4 b0 = *(const float4*)wp;
                float4 b1 = *(const float4*)(wp + 4);
                Bs[(kh+0)*128 + c] = b0.x; Bs[(kh+1)*128 + c] = b0.y;
                Bs[(kh+2)*128 + c] = b0.z; Bs[(kh+3)*128 + c] = b0.w;
                Bs[(kh+4)*128 + c] = b1.x; Bs[(kh+5)*128 + c] = b1.y;
                Bs[(kh+6)*128 + c] = b1.z; Bs[(kh+7)*128 + c] = b1.w;
            }
            __syncthreads();
            #pragma unroll
            for (int kk = 0; kk < 16; kk++) {
                float ar[8], br[8];
                #pragma unroll
                for (int i = 0; i < 8; i++) {
                    ar[i] = As[kk*128 + ty*8 + i];
                    br[i] = Bs[kk*128 + tx*8 + i];
                }
                #pragma unroll
                for (int i = 0; i < 8; i++)
                    #pragma unroll
                    for (int j = 0; j < 8; j++) acc[i][j] += ar[i] * br[j];
            }
            __syncthreads();
        }
        #pragma unroll
        for (int i = 0; i < 8; i++) {
            int r = row0 + ty*8 + i;
            if (r < NN) {
                #pragma unroll
                for (int j = 0; j < 8; j++) {
                    int c = col0 + tx*8 + j;
                    out[(size_t)r*FOUT + c] = acc[i][j] + ob[c];
                }
            }
        }
    }
}

// ---------------- K6: coordinate-function features ----------------------------
__global__ void k_coord(const float* __restrict__ tri, const float* __restrict__ gmu,
                        const float* __restrict__ gsig, const float* __restrict__ lw,
                        const float* __restrict__ rc, const float* __restrict__ rr) {
    int n = blockIdx.x * blockDim.x + threadIdx.x;
    if (n >= NN) return;
    float t0 = tri[0], t1 = tri[1], t2 = tri[2];
    float sig = gsig[0];
    float inv2s2 = 1.f / (2.f * sig * sig);
    float rrv = fabsf(rr[0]);
    float mu[6], lww[6], rcc[6];
    #pragma unroll
    for (int i = 0; i < 6; i++) { mu[i] = gmu[i]; lww[i] = lw[i]; rcc[i] = rc[i]; }

    #pragma unroll
    for (int f = 0; f < NF; f++) {
        float b = g_fall[f*NN + n];
        int  di = g_death[f*NN + n];
        float d = g_fall[f*NN + di];
        float* o = g_coord + (size_t)n*96 + f*12;
        o[0] = fmaxf(0.f, d - fabsf(t0 - b));
        o[1] = fmaxf(0.f, d - fabsf(t1 - b));
        o[2] = fmaxf(0.f, d - fabsf(t2 - b));
        #pragma unroll
        for (int i = 0; i < 3; i++) {
            float dx = b - mu[2*i], dy = d - mu[2*i+1];
            o[3+i] = expf(-(dx*dx + dy*dy) * inv2s2);
        }
        #pragma unroll
        for (int i = 0; i < 3; i++) o[6+i] = b*lww[2*i] + d*lww[2*i+1];
        #pragma unroll
        for (int i = 0; i < 3; i++) {
            float q = fabsf(b - rcc[2*i]) + fabsf(d - rcc[2*i+1]);
            o[9+i] = 1.f/(1.f + q) - 1.f/(1.f + fabsf(rrv - q));
        }
    }
}

// ---------------- K7: out += coord @ W2^T -------------------------------------
__global__ void k_out(const float* __restrict__ ow, float* __restrict__ out) {
    __shared__ float cs[32*96];
    int n0 = blockIdx.x * 32;
    for (int i = threadIdx.x; i < 32*96; i += blockDim.x)
        cs[i] = g_coord[(size_t)n0*96 + i];
    __syncthreads();
    int o = threadIdx.x;                      // 512 threads = FOUT
    float acc[32];
    #pragma unroll
    for (int i = 0; i < 32; i++) acc[i] = 0.f;
    const float* wr = ow + (size_t)o*KTOT + FIN;
    for (int k = 0; k < 96; k++) {
        float w = wr[k];
        #pragma unroll
        for (int i = 0; i < 32; i++) acc[i] += cs[i*96 + k] * w;
    }
    #pragma unroll
    for (int i = 0; i < 32; i++)
        out[(size_t)(n0 + i)*FOUT + o] += acc[i];
}

// ---------------- launcher ----------------------------------------------------
extern "C" void kernel_launch(void* const* d_in, const int* in_sizes, int n_in,
                              void* d_out, int out_size) {
    const float* x    = (const float*)d_in[0];
    const int*   ei   = (const int*)  d_in[1];
    const float* fw   = (const float*)d_in[2];
    const float* fb   = (const float*)d_in[3];
    const float* tri  = (const float*)d_in[4];
    const float* gmu  = (const float*)d_in[5];
    const float* gsig = (const float*)d_in[6];
    const float* lw   = (const float*)d_in[7];
    const float* rc   = (const float*)d_in[8];
    const float* rr   = (const float*)d_in[9];
    const float* ow   = (const float*)d_in[10];
    const float* ob   = (const float*)d_in[11];
    float* out = (float*)d_out;

    cudaFuncSetAttribute(k_fused, cudaFuncAttributeMaxDynamicSharedMemorySize,
                         FUSED_SMEM);
    cudaFuncSetAttribute(k_bv, cudaFuncAttributeMaxDynamicSharedMemorySize,
                         BV_SMEM);

    k_zero   <<<NF*1024, 1024>>>();
    k_filt   <<<(NN + 7) / 8, 256>>>(x, fw, fb);
    k_hist   <<<(NF*EE + 255) / 256, 256>>>(ei);
    k_scan1  <<<NF*1024, 1024>>>();
    k_scan2  <<<NF, 1024>>>();
    k_scan3  <<<NF*1024, 1024>>>();
    k_scatter<<<(NF*EE + 255) / 256, 256>>>(ei);
    k_bsort  <<<(NF*NBK + 255) / 256, 256>>>();

    k_bv    <<<NF, 1024, BV_SMEM>>>();      // MSF prefilter, all-smem Boruvka
    k_cnt   <<<NF*TIL, 256>>>();
    k_cscan <<<NF, 1024>>>();
    k_csct  <<<NF*TIL, 256>>>();

    k_fused  <<<UFB + GM_MT*GM_NT, 256, FUSED_SMEM>>>(x, ow, ob, out);
    k_coord  <<<(NN + 255) / 256, 256>>>(tri, gmu, gsig, lw, rc, rr);
    k_out    <<<NN / 32, 512>>>(ow, out);
}

// round 12
// speedup vs baseline: 5.7195x; 1.3178x over previous
#include <cuda_runtime.h>
#include <cstdint>

#define NN   20000
#define EE   100000
#define NF   8
#define FIN  1024
#define FOUT 512
#define KTOT 1120            // FIN + NF*12
#define NBK  (1u<<20)        // buckets per filtration
#define SHIFT 12
#define UFB  8               // union-find blocks
#define GM_MT 157            // ceil(20000/128)
#define GM_NT 4              // 512/128
#define TIL  391             // ceil(EE/256)
#define BVR  15              // Boruvka rounds (2^15 > 20000)
#define AL_W 3125            // ceil(EE/32) alive-bitmap words
#define FUSED_SMEM (NN*8 + 256*8)           // parent+f + uint2 staging
#define BV_SMEM    (NN*4 + NN*4 + AL_W*4)   // parent + minE + alive = 172500
#define RPT 20               // ceil(NN/1024) roots per thread in k_bv

// ---------------- static device scratch (allowed; no allocations) -------------
__device__ float    g_fall[NF*NN];
__device__ int      g_death[NF*NN];
__device__ unsigned g_hist[NF*NBK];
__device__ unsigned g_offs[NF*NBK];
__device__ unsigned g_cur [NF*NBK];
__device__ unsigned g_bsum[NF*1024];
__device__ uint2    g_recs[NF*EE];
__device__ uint2    g_recs2[NF*EE];
__device__ float    g_coord[NN*96];
__device__ unsigned char g_mflag[NF*EE];
__device__ unsigned g_tile[NF*512];
__device__ unsigned g_cnt[NF];

__device__ __forceinline__ unsigned fkey(float f) {
    unsigned u = __float_as_uint(f);
    return (u & 0x80000000u) ? ~u : (u | 0x80000000u);   // monotone float->uint
}

// ---------------- K0: zero histogram ------------------------------------------
__global__ void k_zero() {
    unsigned i = blockIdx.x * blockDim.x + threadIdx.x;
    if (i < NF*NBK) g_hist[i] = 0u;
}

// ---------------- K1: f_all = x @ filt_w^T + filt_b ----------------------------
__global__ void k_filt(const float* __restrict__ x, const float* __restrict__ fw,
                       const float* __restrict__ fb) {
    __shared__ float ws[NF*FIN];                       // 32 KB
    for (int i = threadIdx.x; i < NF*FIN; i += blockDim.x) ws[i] = fw[i];
    __syncthreads();
    int warp = threadIdx.x >> 5, lane = threadIdx.x & 31;
    int v = blockIdx.x * 8 + warp;
    if (v >= NN) return;
    float acc[NF];
    #pragma unroll
    for (int f = 0; f < NF; f++) acc[f] = 0.f;
    const float* xr = x + (size_t)v * FIN;
    for (int j = lane; j < FIN; j += 32) {
        float xv = xr[j];
        #pragma unroll
        for (int f = 0; f < NF; f++) acc[f] += xv * ws[f*FIN + j];
    }
    #pragma unroll
    for (int f = 0; f < NF; f++) {
        float a = acc[f];
        #pragma unroll
        for (int o = 16; o > 0; o >>= 1) a += __shfl_down_sync(0xffffffffu, a, o);
        if (lane == 0) g_fall[f*NN + v] = a + fb[f];
    }
}

// ---------------- K2: histogram of edge keys ----------------------------------
__global__ void k_hist(const int* __restrict__ ei) {
    unsigned idx = blockIdx.x * blockDim.x + threadIdx.x;
    if (idx >= NF*EE) return;
    unsigned f = idx / EE, e = idx % EE;
    int u = ei[e], v = ei[EE + e];
    float fu = g_fall[f*NN + u], fv = g_fall[f*NN + v];
    unsigned key = fkey(fmaxf(fu, fv));
    atomicAdd(&g_hist[f*NBK + (key >> SHIFT)], 1u);
}

// ---------------- K3: segmented exclusive scan --------------------------------
__device__ __forceinline__ unsigned block_excl_scan_1024(unsigned v, unsigned* wsum) {
    unsigned incl = v;
    int lane = threadIdx.x & 31, wp = threadIdx.x >> 5;
    #pragma unroll
    for (int d = 1; d < 32; d <<= 1) {
        unsigned t = __shfl_up_sync(0xffffffffu, incl, d);
        if (lane >= d) incl += t;
    }
    if (lane == 31) wsum[wp] = incl;
    __syncthreads();
    if (wp == 0) {
        unsigned s = wsum[lane], si = s;
        #pragma unroll
        for (int d = 1; d < 32; d <<= 1) {
            unsigned t = __shfl_up_sync(0xffffffffu, si, d);
            if (lane >= d) si += t;
        }
        wsum[lane] = si - s;
    }
    __syncthreads();
    return incl - v + wsum[wp];
}

__global__ void k_scan1() {
    __shared__ unsigned wsum[32];
    unsigned gi = blockIdx.x * 1024u + threadIdx.x;
    unsigned v = g_hist[gi];
    unsigned excl = block_excl_scan_1024(v, wsum);
    g_offs[gi] = excl;
    if (threadIdx.x == 1023) g_bsum[blockIdx.x] = excl + v;
}

__global__ void k_scan2() {   // NF blocks
    __shared__ unsigned wsum[32];
    unsigned gi = blockIdx.x * 1024u + threadIdx.x;
    unsigned v = g_bsum[gi];
    unsigned excl = block_excl_scan_1024(v, wsum);
    g_bsum[gi] = excl;
}

__global__ void k_scan3() {
    unsigned gi = blockIdx.x * 1024u + threadIdx.x;
    unsigned v = g_offs[gi] + g_bsum[blockIdx.x];
    g_offs[gi] = v;
    g_cur[gi]  = v;
}

// ---------------- K4: scatter edges into bucket-grouped records ---------------
__global__ void k_scatter(const int* __restrict__ ei) {
    unsigned idx = blockIdx.x * blockDim.x + threadIdx.x;
    if (idx >= NF*EE) return;
    unsigned f = idx / EE, e = idx % EE;
    int u = ei[e], v = ei[EE + e];
    float fu = g_fall[f*NN + u], fv = g_fall[f*NN + v];
    unsigned key = fkey(fmaxf(fu, fv));
    unsigned dbit = (fu >= fv) ? 0u : 1u;          // death idx = u if fu>=fv else v
    unsigned pos = atomicAdd(&g_cur[f*NBK + (key >> SHIFT)], 1u);
    g_recs[(size_t)f*EE + pos] =
        make_uint2(key, (unsigned)u | ((unsigned)v << 15) | (dbit << 30));
}

// ---------------- K4.5: sort inside each (tiny) bucket ------------------------
__global__ void k_bsort() {
    unsigned idx = blockIdx.x * blockDim.x + threadIdx.x;
    if (idx >= NF*NBK) return;
    unsigned s = g_offs[idx], e2 = g_cur[idx];     // g_cur now = bucket end
    if (e2 - s < 2) return;
    unsigned f = idx >> 20;
    uint2* r = g_recs + (size_t)f*EE;
    for (unsigned i = s + 1; i < e2; i++) {
        uint2 key = r[i];
        int j = (int)i - 1;
        while (j >= (int)s && r[j].x > key.x) { r[j+1] = r[j]; j--; }
        r[j+1] = key;
    }
}

// =================== Boruvka MSF prefilter: one block / filtration ============
__global__ void __launch_bounds__(1024, 1) k_bv() {
    extern __shared__ char bsm[];
    int*      parent = (int*)bsm;                    // NN
    unsigned* minE   = (unsigned*)(bsm + NN*4);      // NN
    unsigned* alive  = (unsigned*)(bsm + NN*8);      // AL_W words
    const int f = blockIdx.x, tid = threadIdx.x;
    const uint2* recs = g_recs + (size_t)f*EE;
    unsigned char* mf = g_mflag + (size_t)f*EE;

    for (int i = tid; i < NN; i += 1024) { parent[i] = i; minE[i] = 0xFFFFFFFFu; }
    for (int i = tid; i < AL_W; i += 1024) alive[i] = 0xFFFFFFFFu;
    for (int e = tid; e < EE; e += 1024) mf[e] = 0;
    __syncthreads();

    unsigned oth[RPT];
    for (int round = 0; round < BVR; round++) {
        // ---- phase 1: per-edge min-crossing-edge (parent flat, single reads)
        for (int e = tid; e < EE; e += 1024) {
            if (alive[e >> 5] & (1u << (e & 31))) {
                unsigned w = recs[e].y;
                int u = (int)(w & 0x7FFFu), v = (int)((w >> 15) & 0x7FFFu);
                int ra = parent[u], rb = parent[v];
                if (ra == rb) atomicAnd(&alive[e >> 5], ~(1u << (e & 31)));
                else {
                    atomicMin(&minE[ra], (unsigned)e);
                    atomicMin(&minE[rb], (unsigned)e);
                }
            }
        }
        __syncthreads();
        // ---- phase 2a: derive hooks into registers; flag MSF edges
        {
            int k = 0;
            for (int r = tid; r < NN; r += 1024, k++) {
                unsigned o = 0xFFFFFFFFu;
                if (parent[r] == r) {
                    unsigned e = minE[r];
                    if (e != 0xFFFFFFFFu) {
                        unsigned w = recs[e].y;
                        int u = (int)(w & 0x7FFFu), v = (int)((w >> 15) & 0x7FFFu);
                        int ru = parent[u], rv = parent[v];
                        o = (ru == r) ? (unsigned)rv : (unsigned)ru;
                        mf[e] = 1;
                    }
                }
                oth[k] = o;
            }
        }
        __syncthreads();
        // ---- phase 2b: publish hook table (minE repurposed)
        {
            int k = 0;
            for (int r = tid; r < NN; r += 1024, k++) minE[r] = oth[k];
        }
        __syncthreads();
        // ---- phase 2c: commit hooks; break mutual 2-cycles (keep smaller)
        {
            int k = 0;
            for (int r = tid; r < NN; r += 1024, k++) {
                unsigned o = oth[k];
                if (o != 0xFFFFFFFFu && parent[r] == r) {
                    if (!(minE[o] == (unsigned)r && (unsigned)r < o))
                        parent[r] = (int)o;
                }
            }
        }
        __syncthreads();
        // ---- phase 3: pointer-jump flatten (acyclic) + minE reset
        for (int i = tid; i < NN; i += 1024) {
            int r = i, p;
            while ((p = parent[r]) != r) r = p;
            parent[i] = r;
            minE[i] = 0xFFFFFFFFu;
        }
        __syncthreads();
    }
}

// ---------------- compaction (order-preserving) -------------------------------
__global__ void k_cnt() {                           // grid NF*TIL, 256 thr
    __shared__ unsigned wcnt[8];
    unsigned f = blockIdx.x / TIL, tile = blockIdx.x % TIL;
    unsigned i = tile * 256 + threadIdx.x;
    unsigned flag = (i < EE) ? (unsigned)g_mflag[(size_t)f*EE + i] : 0u;
    unsigned bal = __ballot_sync(0xffffffffu, flag);
    if ((threadIdx.x & 31) == 0) wcnt[threadIdx.x >> 5] = __popc(bal);
    __syncthreads();
    if (threadIdx.x == 0) {
        unsigned s = 0;
        #pragma unroll
        for (int w = 0; w < 8; w++) s += wcnt[w];
        g_tile[f*512 + tile] = s;
    }
}

__global__ void k_cscan() {                         // NF blocks, 1024 thr
    __shared__ unsigned wsum[32];
    unsigned f = blockIdx.x;
    unsigned v = (threadIdx.x < TIL) ? g_tile[f*512 + threadIdx.x] : 0u;
    unsigned excl = block_excl_scan_1024(v, wsum);
    if (threadIdx.x < TIL) g_tile[f*512 + threadIdx.x] = excl;
    if (threadIdx.x == TIL - 1) g_cnt[f] = excl + v;
}

__global__ void k_csct() {                          // grid NF*TIL, 256 thr
    __shared__ unsigned woff[8];
    unsigned f = blockIdx.x / TIL, tile = blockIdx.x % TIL;
    unsigned i = tile * 256 + threadIdx.x;
    unsigned flag = (i < EE) ? (unsigned)g_mflag[(size_t)f*EE + i] : 0u;
    unsigned bal = __ballot_sync(0xffffffffu, flag);
    int lane = threadIdx.x & 31, wp = threadIdx.x >> 5;
    if (lane == 0) woff[wp] = __popc(bal);
    __syncthreads();
    if (threadIdx.x == 0) {
        unsigned s = 0;
        #pragma unroll
        for (int w = 0; w < 8; w++) { unsigned t = woff[w]; woff[w] = s; s += t; }
    }
    __syncthreads();
    if (flag) {
        unsigned pos = g_tile[f*512 + tile] + woff[wp]
                     + __popc(bal & ((1u << lane) - 1u));
        g_recs2[(size_t)f*EE + pos] = g_recs[(size_t)f*EE + i];
    }
}

// ---------------- K5: fused UF (precomputed-direction serial) + x@W1 GEMM -----
__global__ void __launch_bounds__(256, 1)
k_fused(const float* __restrict__ x, const float* __restrict__ ow,
        const float* __restrict__ ob, float* __restrict__ out) {
    extern __shared__ char dsm[];
    int tid = threadIdx.x;

    if (blockIdx.x < UFB) {
        const int filt = blockIdx.x;
        int*   parent = (int*)dsm;                       // NN ints
        float* fv     = (float*)(dsm + NN*4);            // NN floats
        uint2* st     = (uint2*)(dsm + NN*8);            // 256 staging entries

        int* deathg = g_death + filt*NN;
        for (int i = tid; i < NN; i += 256) {
            parent[i] = i;
            fv[i] = g_fall[filt*NN + i];
            deathg[i] = i;
        }
        __syncthreads();

        const int cnt = (int)g_cnt[filt];                // compacted MSF stream
        const uint2* recs = g_recs2 + (size_t)filt*EE;
        for (int base = 0; base < cnt; base += 256) {
            int i = base + tid;
            if (i < cnt) {
                uint2 r = recs[i];
                unsigned w = r.y;
                int u = (int)(w & 0x7FFFu), v = (int)((w >> 15) & 0x7FFFu);
                // find + full compression (racy-safe: writes install ancestors)
                int ra = u, p;
                while ((p = parent[ra]) != ra) ra = p;
                int xx = u;
                while (xx != ra) { int nx = parent[xx]; parent[xx] = ra; xx = nx; }
                int rb = v;
                while ((p = parent[rb]) != rb) rb = p;
                xx = v;
                while (xx != rb) { int nx = parent[xx]; parent[xx] = rb; xx = nx; }
                // fv is static -> precompute direction & death index now
                float fa = fv[ra], fb = fv[rb];
                unsigned dir = (fa <= fb) ? 0x40000000u : 0u;
                unsigned di  = (w & 0x40000000u) ? (unsigned)v : (unsigned)u;
                st[tid] = make_uint2((unsigned)ra | ((unsigned)rb << 15) | dir, di);
            }
            __syncthreads();
            if (tid == 0) {
                int lim = min(256, cnt - base);
                for (int t = 0; t < lim; t++) {
                    uint2 s = st[t];
                    int ra = (int)(s.x & 0x7FFFu);
                    int rb = (int)((s.x >> 15) & 0x7FFFu);
                    int di = (int)s.y;
                    int pa = parent[ra], pb = parent[rb];
                    if (pa == ra && pb == rb) {          // fresh hint (hot path)
                        if (s.x & 0x40000000u) { parent[rb] = ra; deathg[rb] = di; }
                        else                   { parent[ra] = rb; deathg[ra] = di; }
                    } else {                             // stale: walk + compress
                        int r1 = ra;
                        while (pa != r1) { r1 = pa; pa = parent[r1]; }
                        parent[ra] = r1;
                        int r2 = rb;
                        while (pb != r2) { r2 = pb; pb = parent[r2]; }
                        parent[rb] = r2;
                        if (r1 == r2) continue;
                        float a = fv[r1], b = fv[r2];
                        if (a <= b) { parent[r2] = r1; deathg[r2] = di; }
                        else        { parent[r1] = r2; deathg[r1] = di; }
                    }
                }
            }
            __syncthreads();
        }
    } else {
        // ----------------- out = x @ W1^T + b  (128x128 tile, fp32) -------------
        int bid = blockIdx.x - UFB;
        int row0 = (bid >> 2) * 128, col0 = (bid & 3) * 128;
        float* As = (float*)dsm;            // [16][128]
        float* Bs = As + 16*128;            // [16][128]
        float acc[8][8];
        #pragma unroll
        for (int i = 0; i < 8; i++)
            #pragma unroll
            for (int j = 0; j < 8; j++) acc[i][j] = 0.f;
        int tx = tid & 15, ty = tid >> 4;

        for (int k0 = 0; k0 < FIN; k0 += 16) {
            {   // load A (x) : 128 rows x 16 k
                int r0t = tid >> 2;
                int kq  = (tid & 3) << 2;
                #pragma unroll
                for (int rr2 = 0; rr2 < 2; rr2++) {
                    int r = r0t + rr2*64;
                    int grow = row0 + r;
                    float4 v4 = (grow < NN)
                        ? *(const float4*)(x + (size_t)grow*FIN + k0 + kq)
                        : make_float4(0.f,0.f,0.f,0.f);
                    As[(kq+0)*128 + r] = v4.x; As[(kq+1)*128 + r] = v4.y;
                    As[(kq+2)*128 + r] = v4.z; As[(kq+3)*128 + r] = v4.w;
                }
            }
            {   // load B (out_w first 1024 cols)
                int c  = tid & 127;
                int kh = (tid >> 7) << 3;
                const float* wp = ow + (size_t)(col0 + c)*KTOT + k0 + kh;
                float4 b0 = *(const float4*)wp;
                float4 b1 = *(const float4*)(wp + 4);
                Bs[(kh+0)*128 + c] = b0.x; Bs[(kh+1)*128 + c] = b0.y;
                Bs[(kh+2)*128 + c] = b0.z; Bs[(kh+3)*128 + c] = b0.w;
                Bs[(kh+4)*128 + c] = b1.x; Bs[(kh+5)*128 + c] = b1.y;
                Bs[(kh+6)*128 + c] = b1.z; Bs[(kh+7)*128 + c] = b1.w;
            }
            __syncthreads();
            #pragma unroll
            for (int kk = 0; kk < 16; kk++) {
                float ar[8], br[8];
                #pragma unroll
                for (int i = 0; i < 8; i++) {
                    ar[i] = As[kk*128 + ty*8 + i];
                    br[i] = Bs[kk*128 + tx*8 + i];
                }
                #pragma unroll
                for (int i = 0; i < 8; i++)
                    #pragma unroll
                    for (int j = 0; j < 8; j++) acc[i][j] += ar[i] * br[j];
            }
            __syncthreads();
        }
        #pragma unroll
        for (int i = 0; i < 8; i++) {
            int r = row0 + ty*8 + i;
            if (r < NN) {
                #pragma unroll
                for (int j = 0; j < 8; j++) {
                    int c = col0 + tx*8 + j;
                    out[(size_t)r*FOUT + c] = acc[i][j] + ob[c];
                }
            }
        }
    }
}

// ---------------- K6: coordinate-function features ----------------------------
__global__ void k_coord(const float* __restrict__ tri, const float* __restrict__ gmu,
                        const float* __restrict__ gsig, const float* __restrict__ lw,
                        const float* __restrict__ rc, const float* __restrict__ rr) {
    int n = blockIdx.x * blockDim.x + threadIdx.x;
    if (n >= NN) return;
    float t0 = tri[0], t1 = tri[1], t2 = tri[2];
    float sig = gsig[0];
    float inv2s2 = 1.f / (2.f * sig * sig);
    float rrv = fabsf(rr[0]);
    float mu[6], lww[6], rcc[6];
    #pragma unroll
    for (int i = 0; i < 6; i++) { mu[i] = gmu[i]; lww[i] = lw[i]; rcc[i] = rc[i]; }

    #pragma unroll
    for (int f = 0; f < NF; f++) {
        float b = g_fall[f*NN + n];
        int  di = g_death[f*NN + n];
        float d = g_fall[f*NN + di];
        float* o = g_coord + (size_t)n*96 + f*12;
        o[0] = fmaxf(0.f, d - fabsf(t0 - b));
        o[1] = fmaxf(0.f, d - fabsf(t1 - b));
        o[2] = fmaxf(0.f, d - fabsf(t2 - b));
        #pragma unroll
        for (int i = 0; i < 3; i++) {
            float dx = b - mu[2*i], dy = d - mu[2*i+1];
            o[3+i] = expf(-(dx*dx + dy*dy) * inv2s2);
        }
        #pragma unroll
        for (int i = 0; i < 3; i++) o[6+i] = b*lww[2*i] + d*lww[2*i+1];
        #pragma unroll
        for (int i = 0; i < 3; i++) {
            float q = fabsf(b - rcc[2*i]) + fabsf(d - rcc[2*i+1]);
            o[9+i] = 1.f/(1.f + q) - 1.f/(1.f + fabsf(rrv - q));
        }
    }
}

// ---------------- K7: out += coord @ W2^T -------------------------------------
__global__ void k_out(const float* __restrict__ ow, float* __restrict__ out) {
    __shared__ float cs[32*96];
    int n0 = blockIdx.x * 32;
    for (int i = threadIdx.x; i < 32*96; i += blockDim.x)
        cs[i] = g_coord[(size_t)n0*96 + i];
    __syncthreads();
    int o = threadIdx.x;                      // 512 threads = FOUT
    float acc[32];
    #pragma unroll
    for (int i = 0; i < 32; i++) acc[i] = 0.f;
    const float* wr = ow + (size_t)o*KTOT + FIN;
    for (int k = 0; k < 96; k++) {
        float w = wr[k];
        #pragma unroll
        for (int i = 0; i < 32; i++) acc[i] += cs[i*96 + k] * w;
    }
    #pragma unroll
    for (int i = 0; i < 32; i++)
        out[(size_t)(n0 + i)*FOUT + o] += acc[i];
}

// ---------------- launcher ----------------------------------------------------
extern "C" void kernel_launch(void* const* d_in, const int* in_sizes, int n_in,
                              void* d_out, int out_size) {
    const float* x    = (const float*)d_in[0];
    const int*   ei   = (const int*)  d_in[1];
    const float* fw   = (const float*)d_in[2];
    const float* fb   = (const float*)d_in[3];
    const float* tri  = (const float*)d_in[4];
    const float* gmu  = (const float*)d_in[5];
    const float* gsig = (const float*)d_in[6];
    const float* lw   = (const float*)d_in[7];
    const float* rc   = (const float*)d_in[8];
    const float* rr   = (const float*)d_in[9];
    const float* ow   = (const float*)d_in[10];
    const float* ob   = (const float*)d_in[11];
    float* out = (float*)d_out;

    cudaFuncSetAttribute(k_fused, cudaFuncAttributeMaxDynamicSharedMemorySize,
                         FUSED_SMEM);
    cudaFuncSetAttribute(k_bv, cudaFuncAttributeMaxDynamicSharedMemorySize,
                         BV_SMEM);

    k_zero   <<<NF*1024, 1024>>>();
    k_filt   <<<(NN + 7) / 8, 256>>>(x, fw, fb);
    k_hist   <<<(NF*EE + 255) / 256, 256>>>(ei);
    k_scan1  <<<NF*1024, 1024>>>();
    k_scan2  <<<NF, 1024>>>();
    k_scan3  <<<NF*1024, 1024>>>();
    k_scatter<<<(NF*EE + 255) / 256, 256>>>(ei);
    k_bsort  <<<(NF*NBK + 255) / 256, 256>>>();

    k_bv    <<<NF, 1024, BV_SMEM>>>();      // MSF prefilter, all-smem Boruvka
    k_cnt   <<<NF*TIL, 256>>>();
    k_cscan <<<NF, 1024>>>();
    k_csct  <<<NF*TIL, 256>>>();

    k_fused  <<<UFB + GM_MT*GM_NT, 256, FUSED_SMEM>>>(x, ow, ob, out);
    k_coord  <<<(NN + 255) / 256, 256>>>(tri, gmu, gsig, lw, rc, rr);
    k_out    <<<NN / 32, 512>>>(ow, out);
}